// round 4
// baseline (speedup 1.0000x reference)
#include <cuda_runtime.h>
#include <math.h>

// Problem constants (fixed by the reference)
#define BATCH 8192
#define NCLS  1000
#define DDIM  4096

#define FT        256   // fused threads: 256 x 4 float4 = 4096 cols (whole D)
#define ROW_CHUNK 256

// ---------------------------------------------------------------------------
// Device scratch (no allocations allowed)
// ---------------------------------------------------------------------------
__device__ int    g_offsets[NCLS + 1];
__device__ int    g_rows[BATCH];
__device__ double g_acc_l1;   // sum over rows of (lse - logit_target)
__device__ double g_acc_l2;   // sum over all BCE elements

// ---------------------------------------------------------------------------
// 1) prep: zero accumulators + histogram + scan + scatter + total_accumulated
// ---------------------------------------------------------------------------
__global__ __launch_bounds__(1024)
void prep_kernel(const int* __restrict__ target, float* __restrict__ total_out) {
    __shared__ int scnt[1024];   // counts -> later cursors
    __shared__ int sscan[1024];  // scan workspace
    const int tid = threadIdx.x;

    if (tid == 0) { g_acc_l1 = 0.0; g_acc_l2 = 0.0; }
    scnt[tid] = 0;
    __syncthreads();

    // histogram via shared atomics; target loaded as int4 (8192 = 2048 int4)
    const int4* t4 = reinterpret_cast<const int4*>(target);
    #pragma unroll
    for (int i = tid; i < BATCH / 4; i += 1024) {
        int4 t = t4[i];
        atomicAdd(&scnt[t.x], 1);
        atomicAdd(&scnt[t.y], 1);
        atomicAdd(&scnt[t.z], 1);
        atomicAdd(&scnt[t.w], 1);
    }
    __syncthreads();

    const int v = scnt[tid];
    if (tid < NCLS) total_out[tid] = (float)v;

    // Hillis-Steele inclusive scan over 1024 lanes
    sscan[tid] = v;
    __syncthreads();
    #pragma unroll
    for (int off = 1; off < 1024; off <<= 1) {
        int t = (tid >= off) ? sscan[tid - off] : 0;
        __syncthreads();
        sscan[tid] += t;
        __syncthreads();
    }

    const int incl = sscan[tid];
    if (tid < NCLS) {
        g_offsets[tid + 1] = incl;
        if (tid == 0) g_offsets[0] = 0;
    }

    // cursors = exclusive offsets; scatter row ids (int4 loads again)
    scnt[tid] = incl - v;
    __syncthreads();
    #pragma unroll
    for (int i = tid; i < BATCH / 4; i += 1024) {
        int4 t = t4[i];
        int b = i * 4;
        g_rows[atomicAdd(&scnt[t.x], 1)] = b;
        g_rows[atomicAdd(&scnt[t.y], 1)] = b + 1;
        g_rows[atomicAdd(&scnt[t.z], 1)] = b + 2;
        g_rows[atomicAdd(&scnt[t.w], 1)] = b + 3;
    }
}

// ---------------------------------------------------------------------------
// 2) fused: one block per class. 256 threads x 4 float4 cover all D=4096.
//    Sums sigmoid(dense_out[row]) over class rows + BCE vs dense_labels[c].
//    Row loop unrolled x2 -> 8 outstanding float4 loads per thread.
//    out_sum is only 4B-aligned (d_out + 1 float) -> scalar stores.
// ---------------------------------------------------------------------------
__device__ __forceinline__ void acc_one(const float4 x4, const float4 y4,
                                        float4& acc, float& bce) {
    acc.x += 1.f / (1.f + __expf(-x4.x));
    acc.y += 1.f / (1.f + __expf(-x4.y));
    acc.z += 1.f / (1.f + __expf(-x4.z));
    acc.w += 1.f / (1.f + __expf(-x4.w));
    bce += fmaxf(x4.x, 0.f) - x4.x * y4.x + log1pf(__expf(-fabsf(x4.x)));
    bce += fmaxf(x4.y, 0.f) - x4.y * y4.y + log1pf(__expf(-fabsf(x4.y)));
    bce += fmaxf(x4.z, 0.f) - x4.z * y4.z + log1pf(__expf(-fabsf(x4.z)));
    bce += fmaxf(x4.w, 0.f) - x4.w * y4.w + log1pf(__expf(-fabsf(x4.w)));
}

__global__ __launch_bounds__(FT)
void fused_kernel(const float* __restrict__ dense_out,
                  const float* __restrict__ dense_labels,
                  float* __restrict__ out_sum) {
    __shared__ int srows[ROW_CHUNK];
    const int c = blockIdx.x;
    // thread's 4 column groups: tid*4 + k*1024
    const int col = threadIdx.x * 4;

    float4 y[4];
    float4 acc[4];
    #pragma unroll
    for (int k = 0; k < 4; k++) {
        y[k] = *reinterpret_cast<const float4*>(
            dense_labels + (size_t)c * DDIM + col + k * 1024);
        acc[k] = make_float4(0.f, 0.f, 0.f, 0.f);
    }
    float bce = 0.f;

    const int s = g_offsets[c];
    const int e = g_offsets[c + 1];

    for (int base = s; base < e; base += ROW_CHUNK) {
        const int n = min(ROW_CHUNK, e - base);
        if (threadIdx.x < n) srows[threadIdx.x] = g_rows[base + threadIdx.x];
        __syncthreads();

        int j = 0;
        for (; j + 1 < n; j += 2) {
            const float* p0 = dense_out + (size_t)srows[j]     * DDIM + col;
            const float* p1 = dense_out + (size_t)srows[j + 1] * DDIM + col;
            float4 a[4], b[4];
            #pragma unroll
            for (int k = 0; k < 4; k++) a[k] = *reinterpret_cast<const float4*>(p0 + k * 1024);
            #pragma unroll
            for (int k = 0; k < 4; k++) b[k] = *reinterpret_cast<const float4*>(p1 + k * 1024);
            #pragma unroll
            for (int k = 0; k < 4; k++) acc_one(a[k], y[k], acc[k], bce);
            #pragma unroll
            for (int k = 0; k < 4; k++) acc_one(b[k], y[k], acc[k], bce);
        }
        if (j < n) {
            const float* p0 = dense_out + (size_t)srows[j] * DDIM + col;
            float4 a[4];
            #pragma unroll
            for (int k = 0; k < 4; k++) a[k] = *reinterpret_cast<const float4*>(p0 + k * 1024);
            #pragma unroll
            for (int k = 0; k < 4; k++) acc_one(a[k], y[k], acc[k], bce);
        }
        __syncthreads();
    }

    // scalar stores: destination only 4B-aligned
    #pragma unroll
    for (int k = 0; k < 4; k++) {
        float* dst = out_sum + (size_t)c * DDIM + col + k * 1024;
        dst[0] = acc[k].x; dst[1] = acc[k].y; dst[2] = acc[k].z; dst[3] = acc[k].w;
    }

    // block-reduce bce -> one double atomic per block
    #pragma unroll
    for (int o = 16; o; o >>= 1) bce += __shfl_xor_sync(0xffffffffu, bce, o);
    __shared__ float sw[FT / 32];
    if ((threadIdx.x & 31) == 0) sw[threadIdx.x >> 5] = bce;
    __syncthreads();
    if (threadIdx.x == 0) {
        float t = 0.f;
        #pragma unroll
        for (int w = 0; w < FT / 32; w++) t += sw[w];
        atomicAdd(&g_acc_l2, (double)t);
    }
}

// ---------------------------------------------------------------------------
// 3) cross-entropy: one WARP per batch row; float4 loads, shuffle-only
//    reduction. 1000 floats = 250 float4 = 7 full lanes-strides + 26.
// ---------------------------------------------------------------------------
#define CE_T 256
__global__ __launch_bounds__(CE_T)
void ce_kernel(const float* __restrict__ logits, const int* __restrict__ target) {
    const int row  = blockIdx.x * (CE_T / 32) + (threadIdx.x >> 5);
    const int lane = threadIdx.x & 31;
    const float4* lrow4 = reinterpret_cast<const float4*>(logits + (size_t)row * NCLS);

    float4 v[8];
    #pragma unroll
    for (int k = 0; k < 7; k++) v[k] = lrow4[lane + k * 32];
    const bool has7 = lane < (250 - 7 * 32);   // 26 remaining float4
    v[7] = has7 ? lrow4[lane + 224]
                : make_float4(-INFINITY, -INFINITY, -INFINITY, -INFINITY);

    float mx = -INFINITY;
    #pragma unroll
    for (int k = 0; k < 8; k++)
        mx = fmaxf(mx, fmaxf(fmaxf(v[k].x, v[k].y), fmaxf(v[k].z, v[k].w)));
    #pragma unroll
    for (int o = 16; o; o >>= 1) mx = fmaxf(mx, __shfl_xor_sync(0xffffffffu, mx, o));

    float sum = 0.f;
    #pragma unroll
    for (int k = 0; k < 7; k++)
        sum += __expf(v[k].x - mx) + __expf(v[k].y - mx) +
               __expf(v[k].z - mx) + __expf(v[k].w - mx);
    if (has7)
        sum += __expf(v[7].x - mx) + __expf(v[7].y - mx) +
               __expf(v[7].z - mx) + __expf(v[7].w - mx);
    #pragma unroll
    for (int o = 16; o; o >>= 1) sum += __shfl_xor_sync(0xffffffffu, sum, o);

    if (lane == 0) {
        float lse = mx + __logf(sum);
        float lt  = logits[(size_t)row * NCLS + target[row]];
        atomicAdd(&g_acc_l1, (double)(lse - lt));
    }
}

// ---------------------------------------------------------------------------
// 4) finalize: one thread, combine accumulators
// ---------------------------------------------------------------------------
__global__ void finalize_kernel(float* __restrict__ out_loss) {
    double loss1 = g_acc_l1 / (double)BATCH;
    double loss2 = g_acc_l2 / ((double)BATCH * (double)DDIM);
    out_loss[0] = (float)(0.5 * loss1 + 0.5 * loss2);
}

// ---------------------------------------------------------------------------
// Launch. Output layout (float32): [loss(1) | dense_output_sum(C*D) | total(C)]
// ---------------------------------------------------------------------------
extern "C" void kernel_launch(void* const* d_in, const int* in_sizes, int n_in,
                              void* d_out, int out_size) {
    const float* logits       = (const float*)d_in[0]; // [B, C]
    const float* dense_out    = (const float*)d_in[1]; // [B, D]
    const int*   target       = (const int*)  d_in[2]; // [B]
    const float* dense_labels = (const float*)d_in[3]; // [C, D]

    float* out       = (float*)d_out;
    float* out_loss  = out;
    float* out_sum   = out + 1;
    float* out_total = out + 1 + (size_t)NCLS * DDIM;

    prep_kernel<<<1, 1024>>>(target, out_total);

    fused_kernel<<<NCLS, FT>>>(dense_out, dense_labels, out_sum);

    ce_kernel<<<BATCH / (CE_T / 32), CE_T>>>(logits, target);

    finalize_kernel<<<1, 1>>>(out_loss);
}

// round 5
// speedup vs baseline: 1.9694x; 1.9694x over previous
#include <cuda_runtime.h>
#include <math.h>

// Problem constants (fixed by the reference)
#define BATCH 8192
#define NCLS  1000
#define DDIM  4096

#define TILE_D     1024
#define NT_D       (DDIM / TILE_D)     // 4 tiles over D
#define NF_BLOCKS  (NCLS * NT_D)       // 4000 fused blocks
#define CE_BLOCKS  (BATCH / 4)         // 2048 CE blocks (4 warps/block, warp-per-row)
#define MEGA_T     128
#define NSLOTS     64

// ---------------------------------------------------------------------------
// Device scratch (no allocations allowed)
// ---------------------------------------------------------------------------
__device__ int    g_offsets[NCLS + 1];
__device__ int    g_rows[BATCH];
__device__ double g_l1_slots[NSLOTS];
__device__ double g_l2_slots[NSLOTS];

// ---------------------------------------------------------------------------
// 1) prep: zero slots + histogram + scan + scatter + total_accumulated
// ---------------------------------------------------------------------------
__global__ __launch_bounds__(1024)
void prep_kernel(const int* __restrict__ target, float* __restrict__ total_out) {
    __shared__ int scnt[1024];   // counts -> later cursors
    __shared__ int sscan[1024];  // scan workspace
    const int tid = threadIdx.x;

    if (tid < NSLOTS) { g_l1_slots[tid] = 0.0; g_l2_slots[tid] = 0.0; }
    scnt[tid] = 0;
    __syncthreads();

    // histogram via shared atomics; target loaded as int4 (8192 = 2048 int4)
    const int4* t4 = reinterpret_cast<const int4*>(target);
    #pragma unroll
    for (int i = tid; i < BATCH / 4; i += 1024) {
        int4 t = t4[i];
        atomicAdd(&scnt[t.x], 1);
        atomicAdd(&scnt[t.y], 1);
        atomicAdd(&scnt[t.z], 1);
        atomicAdd(&scnt[t.w], 1);
    }
    __syncthreads();

    const int v = scnt[tid];
    if (tid < NCLS) total_out[tid] = (float)v;

    // Hillis-Steele inclusive scan over 1024 lanes
    sscan[tid] = v;
    __syncthreads();
    #pragma unroll
    for (int off = 1; off < 1024; off <<= 1) {
        int t = (tid >= off) ? sscan[tid - off] : 0;
        __syncthreads();
        sscan[tid] += t;
        __syncthreads();
    }

    const int incl = sscan[tid];
    if (tid < NCLS) {
        g_offsets[tid + 1] = incl;
        if (tid == 0) g_offsets[0] = 0;
    }

    // cursors = exclusive offsets; scatter row ids
    scnt[tid] = incl - v;
    __syncthreads();
    #pragma unroll
    for (int i = tid; i < BATCH / 4; i += 1024) {
        int4 t = t4[i];
        int b = i * 4;
        g_rows[atomicAdd(&scnt[t.x], 1)] = b;
        g_rows[atomicAdd(&scnt[t.y], 1)] = b + 1;
        g_rows[atomicAdd(&scnt[t.z], 1)] = b + 2;
        g_rows[atomicAdd(&scnt[t.w], 1)] = b + 3;
    }
}

// ---------------------------------------------------------------------------
// Element op: one EX2 serves sigmoid and BCE; __logf instead of log1pf.
//   e = exp(-|x|); r = 1/(1+e); sig = x>=0 ? r : 1-r
//   bce += max(x,0) - x*y + log(1+e)
// ---------------------------------------------------------------------------
__device__ __forceinline__ void elem_op(float x, float y, float& acc, float& bce) {
    const float e = __expf(-fabsf(x));
    const float r = 1.f / (1.f + e);
    acc += (x >= 0.f) ? r : (1.f - r);
    bce += fmaxf(x, 0.f) - x * y + __logf(1.f + e);
}

__device__ __forceinline__ void acc4(const float4 x4, const float4 y4,
                                     float4& acc, float& bce) {
    elem_op(x4.x, y4.x, acc.x, bce);
    elem_op(x4.y, y4.y, acc.y, bce);
    elem_op(x4.z, y4.z, acc.z, bce);
    elem_op(x4.w, y4.w, acc.w, bce);
}

// ---------------------------------------------------------------------------
// 2) mega kernel: bid < NF_BLOCKS -> fused segment-sum+BCE tile
//                 else            -> CE (warp-per-row, 4 rows/block)
// ---------------------------------------------------------------------------
__global__ __launch_bounds__(MEGA_T)
void mega_kernel(const float* __restrict__ dense_out,
                 const float* __restrict__ dense_labels,
                 const float* __restrict__ logits,
                 const int*   __restrict__ target,
                 float* __restrict__ out_sum) {
    const int bid = blockIdx.x;
    const int tid = threadIdx.x;
    __shared__ float sred[MEGA_T / 32];

    if (bid < NF_BLOCKS) {
        // ----- fused role: class c, D-tile of 1024 cols, 2 float4/thread -----
        const int c    = bid >> 2;
        const int col0 = ((bid & 3) * TILE_D) + tid * 4;
        const int col1 = col0 + (TILE_D / 2);

        const float4 y0 = *reinterpret_cast<const float4*>(
            dense_labels + (size_t)c * DDIM + col0);
        const float4 y1 = *reinterpret_cast<const float4*>(
            dense_labels + (size_t)c * DDIM + col1);

        float4 acc0 = make_float4(0.f, 0.f, 0.f, 0.f);
        float4 acc1 = make_float4(0.f, 0.f, 0.f, 0.f);
        float bce = 0.f;

        const int s = g_offsets[c];
        const int e = g_offsets[c + 1];

        int i = s;
        for (; i + 1 < e; i += 2) {
            const int r0 = g_rows[i];
            const int r1 = g_rows[i + 1];
            const float* p0 = dense_out + (size_t)r0 * DDIM;
            const float* p1 = dense_out + (size_t)r1 * DDIM;
            const float4 a0 = *reinterpret_cast<const float4*>(p0 + col0);
            const float4 a1 = *reinterpret_cast<const float4*>(p0 + col1);
            const float4 b0 = *reinterpret_cast<const float4*>(p1 + col0);
            const float4 b1 = *reinterpret_cast<const float4*>(p1 + col1);
            acc4(a0, y0, acc0, bce);
            acc4(a1, y1, acc1, bce);
            acc4(b0, y0, acc0, bce);
            acc4(b1, y1, acc1, bce);
        }
        if (i < e) {
            const float* p0 = dense_out + (size_t)g_rows[i] * DDIM;
            const float4 a0 = *reinterpret_cast<const float4*>(p0 + col0);
            const float4 a1 = *reinterpret_cast<const float4*>(p0 + col1);
            acc4(a0, y0, acc0, bce);
            acc4(a1, y1, acc1, bce);
        }

        // scalar stores: out_sum is only 4B-aligned (d_out + 1 float)
        float* dst0 = out_sum + (size_t)c * DDIM + col0;
        dst0[0] = acc0.x; dst0[1] = acc0.y; dst0[2] = acc0.z; dst0[3] = acc0.w;
        float* dst1 = out_sum + (size_t)c * DDIM + col1;
        dst1[0] = acc1.x; dst1[1] = acc1.y; dst1[2] = acc1.z; dst1[3] = acc1.w;

        // block-reduce bce -> one spread double atomic
        #pragma unroll
        for (int o = 16; o; o >>= 1) bce += __shfl_xor_sync(0xffffffffu, bce, o);
        if ((tid & 31) == 0) sred[tid >> 5] = bce;
        __syncthreads();
        if (tid == 0) {
            float t = sred[0] + sred[1] + sred[2] + sred[3];
            atomicAdd(&g_l2_slots[bid & (NSLOTS - 1)], (double)t);
        }
    } else {
        // ----- CE role: warp-per-row, 4 rows per block -----
        const int rb   = bid - NF_BLOCKS;
        const int warp = tid >> 5;
        const int lane = tid & 31;
        const int row  = rb * 4 + warp;
        const float4* lrow4 =
            reinterpret_cast<const float4*>(logits + (size_t)row * NCLS);

        float4 v[8];
        #pragma unroll
        for (int k = 0; k < 7; k++) v[k] = lrow4[lane + k * 32];
        const bool has7 = lane < (250 - 7 * 32);   // 26 remaining float4
        v[7] = has7 ? lrow4[lane + 224]
                    : make_float4(-INFINITY, -INFINITY, -INFINITY, -INFINITY);

        float mx = -INFINITY;
        #pragma unroll
        for (int k = 0; k < 8; k++)
            mx = fmaxf(mx, fmaxf(fmaxf(v[k].x, v[k].y), fmaxf(v[k].z, v[k].w)));
        #pragma unroll
        for (int o = 16; o; o >>= 1)
            mx = fmaxf(mx, __shfl_xor_sync(0xffffffffu, mx, o));

        float sum = 0.f;
        #pragma unroll
        for (int k = 0; k < 7; k++)
            sum += __expf(v[k].x - mx) + __expf(v[k].y - mx) +
                   __expf(v[k].z - mx) + __expf(v[k].w - mx);
        if (has7)
            sum += __expf(v[7].x - mx) + __expf(v[7].y - mx) +
                   __expf(v[7].z - mx) + __expf(v[7].w - mx);
        #pragma unroll
        for (int o = 16; o; o >>= 1) sum += __shfl_xor_sync(0xffffffffu, sum, o);

        if (lane == 0) {
            float lse = mx + __logf(sum);
            float lt  = logits[(size_t)row * NCLS + target[row]];
            sred[warp] = lse - lt;
        }
        __syncthreads();
        if (tid == 0) {
            float t = sred[0] + sred[1] + sred[2] + sred[3];
            atomicAdd(&g_l1_slots[bid & (NSLOTS - 1)], (double)t);
        }
    }
}

// ---------------------------------------------------------------------------
// 3) finalize: one warp sums 64+64 slot doubles
// ---------------------------------------------------------------------------
__global__ void finalize_kernel(float* __restrict__ out_loss) {
    const int lane = threadIdx.x;   // 32 threads
    double s1 = g_l1_slots[lane] + g_l1_slots[lane + 32];
    double s2 = g_l2_slots[lane] + g_l2_slots[lane + 32];
    #pragma unroll
    for (int o = 16; o; o >>= 1) {
        s1 += __shfl_xor_sync(0xffffffffu, s1, o);
        s2 += __shfl_xor_sync(0xffffffffu, s2, o);
    }
    if (lane == 0) {
        double loss1 = s1 / (double)BATCH;
        double loss2 = s2 / ((double)BATCH * (double)DDIM);
        out_loss[0] = (float)(0.5 * loss1 + 0.5 * loss2);
    }
}

// ---------------------------------------------------------------------------
// Launch. Output layout (float32): [loss(1) | dense_output_sum(C*D) | total(C)]
// ---------------------------------------------------------------------------
extern "C" void kernel_launch(void* const* d_in, const int* in_sizes, int n_in,
                              void* d_out, int out_size) {
    const float* logits       = (const float*)d_in[0]; // [B, C]
    const float* dense_out    = (const float*)d_in[1]; // [B, D]
    const int*   target       = (const int*)  d_in[2]; // [B]
    const float* dense_labels = (const float*)d_in[3]; // [C, D]

    float* out       = (float*)d_out;
    float* out_loss  = out;
    float* out_sum   = out + 1;
    float* out_total = out + 1 + (size_t)NCLS * DDIM;

    prep_kernel<<<1, 1024>>>(target, out_total);

    mega_kernel<<<NF_BLOCKS + CE_BLOCKS, MEGA_T>>>(
        dense_out, dense_labels, logits, target, out_sum);

    finalize_kernel<<<1, 32>>>(out_loss);
}